// round 6
// baseline (speedup 1.0000x reference)
#include <cuda_runtime.h>

// CEHawkesProcess — Hawkes NLL. 2 launches: prep (tables+scalars+femb) + balanced main.
// Inputs (metadata order):
// 0 event_times f32[B*L], 1 event_types i32[B*L], 2 event_categories i32[B*L],
// 3 T (scalar), 4 type_emb f32[NT*E], 5 cat_emb f32[NC*E], 6 a f32[NT*E],
// 7 b f32[NC*E], 8 A f32[NT*NT*E], 9 P f32[NT*NT*E], 10 Bm f32[NC*NC*E],
// 11 Q f32[NC*NC*E].  Output: scalar f32.

namespace {
constexpr int NTY = 50;
constexpr int NCA = 20;
constexpr int EMB = 64;
constexpr int BSZ = 4;
constexpr int SEQ = 256;
constexpr float NL2E = -1.4426950408889634f;  // -log2(e)

constexpr int EVP_BLKS = BSZ * (SEQ / 2);                 // 512  (event pairs i, 255-i)
constexpr int HTP_BLKS = BSZ * (NTY / 2);                 // 100  (horizon type pairs)
constexpr int HC_BLKS = BSZ;                              // 4
constexpr int MAIN_BLKS = EVP_BLKS + HTP_BLKS + HC_BLKS;  // 616 (single wave)

constexpr int TT_BLKS = (NTY * NTY + 15) / 16;            // 157
constexpr int TC_BLKS = (NCA * NCA + 15) / 16;            // 25
constexpr int FB_BLKS = (NTY * NCA + 7) / 8;              // 125
constexpr int BA_BLKS = (NTY + 7) / 8;                    // 7
constexpr int FE_BLKS = 4;                                // f-embedding copy
constexpr int PREP_BLKS = TT_BLKS + TC_BLKS + FB_BLKS + BA_BLKS + FE_BLKS + 1;  // 319
}

// Tables, [target][source][e]: consumer block reads a contiguous slice.
__device__ float2 g_TT[NTY * NTY * EMB];   // {f[t]A[k,t]f[k], NL2E*f[t]P[k,t]f[k]}
__device__ float2 g_TC[NCA * NCA * EMB];   // {g[c2]Bm[c1,c2]g[c1], NL2E*g[c2]Q[c1,c2]g[c1]}
__device__ float g_FEmb[NTY * EMB];        // copy of type_emb
__device__ float g_BA[NTY];                // sum_e f*a
__device__ float g_SP[NTY];                // sum_e softplus(f*a)
__device__ float g_FB[NTY * NCA];          // sum_e f[t]*b[c]
__device__ float g_Fsum[EMB];              // sum_t f[t,e]
__device__ float g_SFB[NCA];               // sum_t FB[t,c]
__device__ float g_Sba, g_I0;
__device__ float g_part[MAIN_BLKS];
__device__ unsigned g_done;                // zero-init; finalizer resets (replay-safe)

struct alignas(16) Ent { float t; int ko; int co; int pad; };

__device__ __forceinline__ float fast_exp2(float x) {
    float r;
    asm("ex2.approx.ftz.f32 %0, %1;" : "=f"(r) : "f"(x));
    return r;
}

__device__ __forceinline__ float softplusf(float x) {
    return fmaxf(x, 0.f) + log1pf(expf(-fabsf(x)));
}

// T may arrive as int32 (value 128) or float32 bits; disambiguate.
__device__ __forceinline__ float readT(const void* p) {
    int v = *(const int*)p;
    return (v > 0 && v < (1 << 24)) ? (float)v : __int_as_float(v);
}

__device__ __forceinline__ float warp_reduce(float v) {
    #pragma unroll
    for (int o = 16; o; o >>= 1) v += __shfl_down_sync(0xffffffffu, v, o);
    return v;
}

__device__ __forceinline__ float block_reduce_256(float v, float* sred) {
    v = warp_reduce(v);
    int tid = threadIdx.x;
    if ((tid & 31) == 0) sred[tid >> 5] = v;
    __syncthreads();
    float r = 0.f;
    if (tid == 0) {
        #pragma unroll
        for (int w = 0; w < 8; w++) r += sred[w];
    }
    return r;
}

// ======================= prep: tables + scalars + femb, all parallel =========
__global__ void __launch_bounds__(256) k_prep(
    const float* __restrict__ f, const float* __restrict__ g,
    const float* __restrict__ a, const float* __restrict__ b,
    const float* __restrict__ A, const float* __restrict__ P,
    const float* __restrict__ Bm, const float* __restrict__ Q) {
    int bid = blockIdx.x;
    int tid = threadIdx.x;

    if (bid < TT_BLKS) {
        int p = bid * 16 + (tid >> 4);          // p = t*NTY + k (write row)
        if (p < NTY * NTY) {
            int e = (tid & 15) << 2;
            int t = p / NTY, k = p - t * NTY;
            int rd = (k * NTY + t) * EMB + e;   // A/P stored [k][t][e]
            float4 Av = *(const float4*)(A + rd);
            float4 Pv = *(const float4*)(P + rd);
            float4 ft = *(const float4*)(f + t * EMB + e);
            float4 fk = *(const float4*)(f + k * EMB + e);
            float w0 = ft.x * fk.x, w1 = ft.y * fk.y;
            float w2 = ft.z * fk.z, w3 = ft.w * fk.w;
            float4* dst = (float4*)(g_TT + p * EMB + e);
            dst[0] = make_float4(w0 * Av.x, NL2E * w0 * Pv.x, w1 * Av.y, NL2E * w1 * Pv.y);
            dst[1] = make_float4(w2 * Av.z, NL2E * w2 * Pv.z, w3 * Av.w, NL2E * w3 * Pv.w);
        }
        return;
    }
    bid -= TT_BLKS;
    if (bid < TC_BLKS) {
        int p = bid * 16 + (tid >> 4);          // p = c2*NCA + c1 (write row)
        if (p < NCA * NCA) {
            int e = (tid & 15) << 2;
            int c2 = p / NCA, c1 = p - c2 * NCA;
            int rd = (c1 * NCA + c2) * EMB + e; // Bm/Q stored [c1][c2][e]
            float4 Bv = *(const float4*)(Bm + rd);
            float4 Qv = *(const float4*)(Q + rd);
            float4 g2 = *(const float4*)(g + c2 * EMB + e);
            float4 g1 = *(const float4*)(g + c1 * EMB + e);
            float w0 = g2.x * g1.x, w1 = g2.y * g1.y;
            float w2 = g2.z * g1.z, w3 = g2.w * g1.w;
            float4* dst = (float4*)(g_TC + p * EMB + e);
            dst[0] = make_float4(w0 * Bv.x, NL2E * w0 * Qv.x, w1 * Bv.y, NL2E * w1 * Qv.y);
            dst[1] = make_float4(w2 * Bv.z, NL2E * w2 * Qv.z, w3 * Bv.w, NL2E * w3 * Qv.w);
        }
        return;
    }
    bid -= TC_BLKS;
    if (bid < FB_BLKS) {
        int w = tid >> 5, lane = tid & 31;
        int idx = bid * 8 + w;
        if (idx < NTY * NCA) {
            int t = idx / NCA, c = idx - t * NCA;
            float s = f[t * EMB + lane] * b[c * EMB + lane]
                    + f[t * EMB + lane + 32] * b[c * EMB + lane + 32];
            s = warp_reduce(s);
            if (lane == 0) g_FB[idx] = s;
        }
        return;
    }
    bid -= FB_BLKS;
    if (bid < BA_BLKS) {
        int w = tid >> 5, lane = tid & 31;
        int t = bid * 8 + w;
        if (t < NTY) {
            float x0 = f[t * EMB + lane] * a[t * EMB + lane];
            float x1 = f[t * EMB + lane + 32] * a[t * EMB + lane + 32];
            float ba = warp_reduce(x0 + x1);
            float sp = warp_reduce(softplusf(x0) + softplusf(x1));
            if (lane == 0) { g_BA[t] = ba; g_SP[t] = sp; }
        }
        return;
    }
    bid -= BA_BLKS;
    if (bid < FE_BLKS) {
        int idx4 = bid * 256 + tid;             // float4 index; 800 total
        if (idx4 < (NTY * EMB) / 4)
            ((float4*)g_FEmb)[idx4] = ((const float4*)f)[idx4];
        return;
    }
    // ---- final scalar block: Fsum, SFB, Sba, I0 ----
    __shared__ float fs_sh[EMB];
    __shared__ float sred1[8];
    __shared__ float sred2[8];
    if (tid < EMB) {
        float s = 0.f;
        #pragma unroll
        for (int t = 0; t < NTY; t++) s += f[t * EMB + tid];
        g_Fsum[tid] = s;
        fs_sh[tid] = s;
    }
    float sba = 0.f, i0 = 0.f;
    for (int idx = tid; idx < NTY * EMB; idx += 256) {
        float x = f[idx] * a[idx];
        sba += x;
        i0 += softplusf(x);
    }
    sba = warp_reduce(sba);
    i0 = warp_reduce(i0);
    if ((tid & 31) == 0) { sred1[tid >> 5] = sba; sred2[tid >> 5] = i0; }
    __syncthreads();
    if (tid == 0) {
        float s = 0.f, s2 = 0.f;
        #pragma unroll
        for (int w = 0; w < 8; w++) { s += sred1[w]; s2 += sred2[w]; }
        g_Sba = s;
        g_I0 = s2;
    }
    {
        int w = tid >> 5, lane = tid & 31;
        for (int c = w; c < NCA; c += 8) {
            float s = fs_sh[lane] * b[c * EMB + lane]
                    + fs_sh[lane + 32] * b[c * EMB + lane + 32];
            s = warp_reduce(s);
            if (lane == 0) g_SFB[c] = s;
        }
    }
}

// ======================= main: balanced paired blocks ========================
__global__ void __launch_bounds__(256, 5) k_main(
    const float* __restrict__ times, const int* __restrict__ types,
    const int* __restrict__ cats, const void* __restrict__ Tp,
    float* __restrict__ out) {
    int bid = blockIdx.x;
    int tid = threadIdx.x;
    __shared__ Ent sh[SEQ];
    __shared__ float sredA[8];
    __shared__ float sredB[8];
    __shared__ double dred[8];
    __shared__ int sh_last;

    int e = tid & (EMB - 1);
    int ch = tid >> 6;  // 0..3
    float partial = 0.f;

    if (bid < EVP_BLKS) {
        // ---- event pair (i_hi = 255-p, i_lo = p) with fused shared-prefix ----
        int bb = bid & 3;
        int p = bid >> 2;                   // 0..127
        int i_hi = (SEQ - 1) - p;           // 128..255
        int i_lo = p;                       // 0..127
        const float* ts = times + bb * SEQ;
        const int* ty = types + bb * SEQ;
        const int* ct = cats + bb * SEQ;

        for (int s = tid; s < i_hi; s += 256) {
            Ent en;
            en.t = ts[s];
            en.ko = ty[s] * EMB;
            en.co = ct[s] * EMB;
            en.pad = 0;
            sh[s] = en;
        }
        __syncthreads();

        int tiH = ty[i_hi];
        float tH = ts[i_hi];
        int lcH = ct[i_hi - 1];
        const float2* __restrict__ ttbH = g_TT + (size_t)tiH * (NTY * EMB) + e;
        const float2* __restrict__ tcbH = g_TC + (size_t)lcH * (NCA * EMB) + e;

        float hT0 = 0.f, hT1 = 0.f, hC0 = 0.f, hC1 = 0.f;   // event i_hi accums
        float lT0 = 0.f, lT1 = 0.f, lC0 = 0.f, lC1 = 0.f;   // event i_lo accums
        int s = ch;

        if (i_lo > 0) {
            int tiL = ty[i_lo];
            float tL = ts[i_lo];
            int lcL = ct[i_lo - 1];
            const float2* __restrict__ ttbL = g_TT + (size_t)tiL * (NTY * EMB) + e;
            const float2* __restrict__ tcbL = g_TC + (size_t)lcL * (NCA * EMB) + e;

            // fused prefix: s < i_lo feeds BOTH events (one LDS per item)
            for (; s + 4 < i_lo; s += 8) {
                Ent e0 = sh[s], e1 = sh[s + 4];
                float2 tH0 = __ldg(ttbH + e0.ko);
                float2 cH0 = __ldg(tcbH + e0.co);
                float2 tL0 = __ldg(ttbL + e0.ko);
                float2 cL0 = __ldg(tcbL + e0.co);
                float2 tH1 = __ldg(ttbH + e1.ko);
                float2 cH1 = __ldg(tcbH + e1.co);
                float2 tL1 = __ldg(ttbL + e1.ko);
                float2 cL1 = __ldg(tcbL + e1.co);
                float dH0 = tH - e0.t, dL0 = tL - e0.t;
                float dH1 = tH - e1.t, dL1 = tL - e1.t;
                hT0 = fmaf(tH0.x, fast_exp2(tH0.y * dH0), hT0);
                hC0 = fmaf(cH0.x, fast_exp2(cH0.y * dH0), hC0);
                lT0 = fmaf(tL0.x, fast_exp2(tL0.y * dL0), lT0);
                lC0 = fmaf(cL0.x, fast_exp2(cL0.y * dL0), lC0);
                hT1 = fmaf(tH1.x, fast_exp2(tH1.y * dH1), hT1);
                hC1 = fmaf(cH1.x, fast_exp2(cH1.y * dH1), hC1);
                lT1 = fmaf(tL1.x, fast_exp2(tL1.y * dL1), lT1);
                lC1 = fmaf(cL1.x, fast_exp2(cL1.y * dL1), lC1);
            }
            for (; s < i_lo; s += 4) {
                Ent e0 = sh[s];
                float2 tH0 = __ldg(ttbH + e0.ko);
                float2 cH0 = __ldg(tcbH + e0.co);
                float2 tL0 = __ldg(ttbL + e0.ko);
                float2 cL0 = __ldg(tcbL + e0.co);
                float dH0 = tH - e0.t, dL0 = tL - e0.t;
                hT0 = fmaf(tH0.x, fast_exp2(tH0.y * dH0), hT0);
                hC0 = fmaf(cH0.x, fast_exp2(cH0.y * dH0), hC0);
                lT0 = fmaf(tL0.x, fast_exp2(tL0.y * dL0), lT0);
                lC0 = fmaf(cL0.x, fast_exp2(cL0.y * dL0), lC0);
            }
            // reduce event i_lo
            float fevL = g_FEmb[tiL * EMB + e];
            float accL = (lT0 + lT1) + fevL * (lC0 + lC1);
            float totL = block_reduce_256(accL, sredB);
            if (tid == 0 && tL >= 0.f) {
                float lam = g_BA[tiL] + g_FB[tiL * NCA + lcL] + totL;
                partial = -(logf(lam + 1e-16f) + lam);
            }
        } else {
            if (tid == 0 && ts[0] >= 0.f) {
                float lam = g_SP[ty[0]];
                partial = -(logf(lam + 1e-16f) + lam);
            }
        }

        // remainder: s in [i_lo, i_hi) feeds only event i_hi (4-way unroll)
        for (; s + 12 < i_hi; s += 16) {
            Ent e0 = sh[s], e1 = sh[s + 4], e2 = sh[s + 8], e3 = sh[s + 12];
            float2 t0 = __ldg(ttbH + e0.ko);
            float2 c0 = __ldg(tcbH + e0.co);
            float2 t1 = __ldg(ttbH + e1.ko);
            float2 c1 = __ldg(tcbH + e1.co);
            float2 t2 = __ldg(ttbH + e2.ko);
            float2 c2 = __ldg(tcbH + e2.co);
            float2 t3 = __ldg(ttbH + e3.ko);
            float2 c3 = __ldg(tcbH + e3.co);
            float d0 = tH - e0.t, d1 = tH - e1.t;
            float d2 = tH - e2.t, d3 = tH - e3.t;
            hT0 = fmaf(t0.x, fast_exp2(t0.y * d0), hT0);
            hC0 = fmaf(c0.x, fast_exp2(c0.y * d0), hC0);
            hT1 = fmaf(t1.x, fast_exp2(t1.y * d1), hT1);
            hC1 = fmaf(c1.x, fast_exp2(c1.y * d1), hC1);
            hT0 = hT0; hC0 = hC0;
            hT0 = fmaf(t2.x, fast_exp2(t2.y * d2), hT0);
            hC0 = fmaf(c2.x, fast_exp2(c2.y * d2), hC0);
            hT1 = fmaf(t3.x, fast_exp2(t3.y * d3), hT1);
            hC1 = fmaf(c3.x, fast_exp2(c3.y * d3), hC1);
        }
        for (; s < i_hi; s += 4) {
            Ent e0 = sh[s];
            float2 t0 = __ldg(ttbH + e0.ko);
            float2 c0 = __ldg(tcbH + e0.co);
            float d0 = tH - e0.t;
            hT0 = fmaf(t0.x, fast_exp2(t0.y * d0), hT0);
            hC0 = fmaf(c0.x, fast_exp2(c0.y * d0), hC0);
        }
        float fevH = g_FEmb[tiH * EMB + e];
        float accH = (hT0 + hT1) + fevH * (hC0 + hC1);
        float totH = block_reduce_256(accH, sredA);
        if (tid == 0 && tH >= 0.f) {
            float lam = g_BA[tiH] + g_FB[tiH * NCA + lcH] + totH;
            partial += -(logf(lam + 1e-16f) + lam);
        }
    } else if (bid < EVP_BLKS + HTP_BLKS) {
        // ---- horizon type pair: (b, t) and (b, t+25) ----
        int idx0 = bid - EVP_BLKS;
        int bb = idx0 / (NTY / 2);
        int tp = idx0 - bb * (NTY / 2);     // 0..24
        float Tf = readT(Tp);
        const float* ts = times + bb * SEQ;
        const int* ty = types + bb * SEQ;
        for (int s = tid; s < SEQ; s += 256) {
            Ent en; en.t = ts[s]; en.ko = ty[s] * EMB; en.co = 0; en.pad = 0;
            sh[s] = en;
        }
        __syncthreads();
        float tgap = Tf - sh[SEQ - 1].t;
        float* sr = sredA;
        #pragma unroll
        for (int half = 0; half < 2; half++) {
            int t = tp + half * (NTY / 2);
            const float2* __restrict__ ttb = g_TT + (size_t)t * (NTY * EMB) + e;
            float a0 = 0.f, a1 = 0.f, a2 = 0.f, a3 = 0.f;
            #pragma unroll 2
            for (int s = ch; s < SEQ; s += 16) {
                Ent e0 = sh[s], e1 = sh[s + 4], e2 = sh[s + 8], e3 = sh[s + 12];
                float2 w0 = __ldg(ttb + e0.ko);
                float2 w1 = __ldg(ttb + e1.ko);
                float2 w2 = __ldg(ttb + e2.ko);
                float2 w3 = __ldg(ttb + e3.ko);
                a0 = fmaf(w0.x, fast_exp2(w0.y * (Tf - e0.t)), a0);
                a1 = fmaf(w1.x, fast_exp2(w1.y * (Tf - e1.t)), a1);
                a2 = fmaf(w2.x, fast_exp2(w2.y * (Tf - e2.t)), a2);
                a3 = fmaf(w3.x, fast_exp2(w3.y * (Tf - e3.t)), a3);
            }
            float total = block_reduce_256((a0 + a1) + (a2 + a3), sr);
            if (tid == 0) partial += total * tgap;
            sr = sredB;
        }
    } else {
        // ---- horizon category channel: b ----
        int bb = bid - EVP_BLKS - HTP_BLKS;
        float Tf = readT(Tp);
        const float* ts = times + bb * SEQ;
        const int* ct = cats + bb * SEQ;
        for (int s = tid; s < SEQ; s += 256) {
            Ent en; en.t = ts[s]; en.co = ct[s] * EMB; en.ko = 0; en.pad = 0;
            sh[s] = en;
        }
        __syncthreads();
        int lcL = ct[SEQ - 1];
        const float2* __restrict__ tcb = g_TC + (size_t)lcL * (NCA * EMB) + e;
        float a0 = 0.f, a1 = 0.f, a2 = 0.f, a3 = 0.f;
        #pragma unroll 2
        for (int s = ch; s < SEQ; s += 16) {
            Ent e0 = sh[s], e1 = sh[s + 4], e2 = sh[s + 8], e3 = sh[s + 12];
            float2 w0 = __ldg(tcb + e0.co);
            float2 w1 = __ldg(tcb + e1.co);
            float2 w2 = __ldg(tcb + e2.co);
            float2 w3 = __ldg(tcb + e3.co);
            a0 = fmaf(w0.x, fast_exp2(w0.y * (Tf - e0.t)), a0);
            a1 = fmaf(w1.x, fast_exp2(w1.y * (Tf - e1.t)), a1);
            a2 = fmaf(w2.x, fast_exp2(w2.y * (Tf - e2.t)), a2);
            a3 = fmaf(w3.x, fast_exp2(w3.y * (Tf - e3.t)), a3);
        }
        float acc = ((a0 + a1) + (a2 + a3)) * g_Fsum[e];
        float total = block_reduce_256(acc, sredA);
        if (tid == 0) partial = total * (Tf - sh[SEQ - 1].t);
    }

    // ---- publish partial + grid-completion finalizer ----
    if (tid == 0) {
        g_part[bid] = partial;
        __threadfence();
        unsigned n = atomicAdd(&g_done, 1u);
        sh_last = (n == (unsigned)(MAIN_BLKS - 1)) ? 1 : 0;
        if (sh_last) __threadfence();
    }
    __syncthreads();
    if (sh_last) {
        double v = 0.0;
        for (int idx = tid; idx < MAIN_BLKS; idx += 256) v += (double)g_part[idx];
        #pragma unroll
        for (int o = 16; o; o >>= 1) v += __shfl_down_sync(0xffffffffu, v, o);
        if ((tid & 31) == 0) dred[tid >> 5] = v;
        __syncthreads();
        if (tid == 0) {
            double r = 0.0;
            #pragma unroll
            for (int w = 0; w < 8; w++) r += dred[w];
            float Tf = readT(Tp);
            for (int b2 = 0; b2 < BSZ; b2++) {
                int lcL = cats[b2 * SEQ + SEQ - 1];
                float tlast = times[b2 * SEQ + SEQ - 1];
                float t0 = times[b2 * SEQ];
                r += (double)((g_Sba + g_SFB[lcL]) * (Tf - tlast) + g_I0 * t0);
            }
            out[0] = (float)r;
            g_done = 0u;  // reset for next replay
        }
    }
}

extern "C" void kernel_launch(void* const* d_in, const int* in_sizes, int n_in,
                              void* d_out, int out_size) {
    const float* times = (const float*)d_in[0];
    const int* types = (const int*)d_in[1];
    const int* cats = (const int*)d_in[2];
    const void* Tp = d_in[3];
    const float* type_emb = (const float*)d_in[4];
    const float* cat_emb = (const float*)d_in[5];
    const float* a = (const float*)d_in[6];
    const float* b = (const float*)d_in[7];
    const float* A = (const float*)d_in[8];
    const float* P = (const float*)d_in[9];
    const float* Bm = (const float*)d_in[10];
    const float* Q = (const float*)d_in[11];
    float* out = (float*)d_out;

    k_prep<<<PREP_BLKS, 256>>>(type_emb, cat_emb, a, b, A, P, Bm, Q);
    k_main<<<MAIN_BLKS, 256>>>(times, types, cats, Tp, out);
}